// round 7
// baseline (speedup 1.0000x reference)
#include <cuda_runtime.h>
#include <cuda_fp16.h>
#include <cstdint>
#include <math.h>

#define BATCH 64
#define LSEQ  48
#define EDIM  300
#define F0DIM 300
#define NEGV  (-1000000000.0f)

// ---------------- helpers ----------------
__device__ __forceinline__ uint32_t smem_u32(const void* p) {
    uint32_t a;
    asm("{ .reg .u64 t; cvta.to.shared.u64 t, %1; cvt.u32.u64 %0, t; }"
        : "=r"(a) : "l"(p));
    return a;
}
#define LDSM4(r, addr) \
    asm volatile("ldmatrix.sync.aligned.m8n8.x4.shared.b16 {%0,%1,%2,%3}, [%4];" \
        : "=r"((r)[0]), "=r"((r)[1]), "=r"((r)[2]), "=r"((r)[3]) : "r"(addr))
#define LDSM2(r, addr) \
    asm volatile("ldmatrix.sync.aligned.m8n8.x2.shared.b16 {%0,%1}, [%2];" \
        : "=r"((r)[0]), "=r"((r)[1]) : "r"(addr))
#define MMA16816(c, a, bb) \
    asm volatile("mma.sync.aligned.m16n8k16.row.col.f32.f16.f16.f32 " \
        "{%0,%1,%2,%3}, {%4,%5,%6,%7}, {%8,%9}, {%0,%1,%2,%3};" \
        : "+f"((c)[0]), "+f"((c)[1]), "+f"((c)[2]), "+f"((c)[3]) \
        : "r"((a)[0]), "r"((a)[1]), "r"((a)[2]), "r"((a)[3]), \
          "r"((bb)[0]), "r"((bb)[1]))

// order-preserving float<->uint for atomic max
__device__ __forceinline__ unsigned enc_f(float x) {
    unsigned u = __float_as_uint(x);
    return (u & 0x80000000u) ? ~u : (u | 0x80000000u);
}
__device__ __forceinline__ float dec_f(unsigned k) {
    unsigned u = (k & 0x80000000u) ? (k & 0x7fffffffu) : ~k;
    return __uint_as_float(u);
}

// ---------------- global scratch ----------------
__device__ float g_R[128 * LSEQ * EDIM];            // r1 (0..63), r2 (64..127)
__device__ float g_Racc[3][128 * LSEQ * EDIM];      // per-tap conv partials
__device__ unsigned g_Su[2 * 64 * 48 * 304];        // s1 | s2 encoded max (pre-tanh)
__device__ float g_H[64 * 600];
__device__ float g_J[64 * 300];
// fc0 weights, fp16 hi/lo split, layout [fc(3)][chunk(10)][n(112)][k(64)]
__device__ uint4 g_W4h[3 * 10 * 112 * 64 / 8];
__device__ uint4 g_W4l[3 * 10 * 112 * 64 / 8];
// conv weights, fp16 hi/lo, layout [t(3)][n(320)][k(320)]
__device__ __half g_CWh[3 * 320 * 320];
__device__ __half g_CWl[3 * 320 * 320];

#define S2_OFF (64 * 48 * 304)   // 933888

// ---------------------------------------------------------------------------
// prep_w: fc0_w -> fp16 hi/lo split in joint CTA-chunk layout
// ---------------------------------------------------------------------------
__global__ void prep_w(const float* __restrict__ fc0_w) {
    int fcc = blockIdx.x;           // fc*10 + c
    int fc = fcc / 10, c = fcc % 10;
    int n = blockIdx.y, k = threadIdx.x;
    int f = fc * 112 + n;
    int kg = c * 64 + k;
    float v = (f < 300 && kg < 600) ? fc0_w[(size_t)f * 600 + kg] : 0.f;
    __half h = __float2half_rn(v);
    __half l = __float2half_rn(v - __half2float(h));
    size_t idx = ((size_t)fcc * 112 + n) * 64 + k;
    ((__half*)g_W4h)[idx] = h;
    ((__half*)g_W4l)[idx] = l;
}

// prep_cw: conv_w (E,E,3) -> W_t[n=eo][k=ei] fp16 hi/lo, zero-padded to 320x320
__global__ void prep_cw(const float* __restrict__ conv_w) {
    int t = blockIdx.x, n = blockIdx.y, k = threadIdx.x;
    float v = (n < 300 && k < 300) ? conv_w[(size_t)n * 900 + k * 3 + t] : 0.f;
    __half h = __float2half_rn(v);
    __half l = __float2half_rn(v - __half2float(h));
    size_t idx = ((size_t)t * 320 + n) * 320 + k;
    g_CWh[idx] = h;
    g_CWl[idx] = l;
}

// init_s: seed encoded NEG
__global__ void init_s() {
    unsigned idx = blockIdx.x * 256 + threadIdx.x;
    if (idx < 2u * S2_OFF) g_Su[idx] = ~__float_as_uint(NEGV);
}

// ---------------------------------------------------------------------------
// encode_tc: HMMA conv1d partial (ONE tap per CTA).
// grid (128, 2, 3): x = s, y = nh (eo half of 160), z = tap. 192 threads.
// Writes raw partial sums to g_Racc[t]; finalize_enc combines.
// ---------------------------------------------------------------------------
#define XSTR 328
#define EBST 72
#define OF_XH 0
#define OF_XL 32800
#define OF_EBH 65600
#define OF_EBL 88640
#define OF_TOK 111680
#define SME_TOTAL 111872

__global__ __launch_bounds__(192) void encode_tc(
    const int* __restrict__ q1, const int* __restrict__ q2,
    const float* __restrict__ emb)
{
    int s = blockIdx.x, nh = blockIdx.y, t = blockIdx.z;
    int b = s & 63;
    bool side = s >= 64;
    extern __shared__ char smc[];
    __half* xh = (__half*)(smc + OF_XH);   // [50][XSTR], row r = x[r-1]
    __half* xl = (__half*)(smc + OF_XL);
    __half* sbh = (__half*)(smc + OF_EBH); // [160][EBST]
    __half* sbl = (__half*)(smc + OF_EBL);
    int* toks = (int*)(smc + OF_TOK);
    int tid = threadIdx.x, warp = tid >> 5, lane = tid & 31;
    const int* q = side ? q2 : q1;

    if (tid < 48) toks[tid] = q[b * 48 + tid];
    for (int i = tid; i < 4100; i += 192) ((uint4*)smc)[i] = make_uint4(0, 0, 0, 0);
    __syncthreads();
    for (int i = tid; i < 48 * 300; i += 192) {
        int l = i / 300, ei = i - l * 300;
        float v = emb[(size_t)toks[l] * 300 + ei];
        __half h = __float2half_rn(v);
        xh[(l + 1) * XSTR + ei] = h;
        xl[(l + 1) * XSTR + ei] = __float2half_rn(v - __half2float(h));
    }

    int mw = warp >> 1, nw = warp & 1;
    float acc[10][4];
    #pragma unroll
    for (int n8 = 0; n8 < 10; n8++)
        #pragma unroll
        for (int v = 0; v < 4; v++) acc[n8][v] = 0.f;

    uint32_t sbase = smem_u32(smc);
    uint32_t aXh = sbase + OF_XH + (uint32_t)((mw * 16 + (lane & 15)) * XSTR + ((lane >> 4) << 3)) * 2;
    uint32_t aXl = aXh + (OF_XL - OF_XH);
    uint32_t aBh = sbase + OF_EBH + (uint32_t)((nw * 80 + (lane & 7)) * EBST + (lane & 8)) * 2;
    uint32_t aBl = aBh + (OF_EBL - OF_EBH);

    const __half* gwh = g_CWh + ((size_t)t * 320 + nh * 160) * 320;
    const __half* gwl = g_CWl + ((size_t)t * 320 + nh * 160) * 320;
    for (int c = 0; c < 5; c++) {
        __syncthreads();
        {
            const uint4* sh = (const uint4*)(gwh + c * 64);
            const uint4* sl = (const uint4*)(gwl + c * 64);
            for (int i = tid; i < 160 * 8; i += 192) {
                int n = i >> 3, kk = i & 7;
                *(uint4*)(sbh + n * EBST + kk * 8) = sh[n * 40 + kk];
                *(uint4*)(sbl + n * EBST + kk * 8) = sl[n * 40 + kk];
            }
        }
        __syncthreads();
        uint32_t aoff = (uint32_t)(t * XSTR + c * 64) * 2;
        #pragma unroll
        for (int ks = 0; ks < 4; ks++) {
            uint32_t k2 = ks * 32;
            uint32_t ah[4], al[4], bhf[10][2], blf[10][2];
            LDSM4(ah, aXh + aoff + k2);
            LDSM4(al, aXl + aoff + k2);
            #pragma unroll
            for (int n8 = 0; n8 < 10; n8++) LDSM2(bhf[n8], aBh + (uint32_t)(n8 * 8 * EBST) * 2 + k2);
            #pragma unroll
            for (int n8 = 0; n8 < 10; n8++) MMA16816(acc[n8], ah, bhf[n8]);
            #pragma unroll
            for (int n8 = 0; n8 < 10; n8++) MMA16816(acc[n8], al, bhf[n8]);
            #pragma unroll
            for (int n8 = 0; n8 < 10; n8++) LDSM2(blf[n8], aBl + (uint32_t)(n8 * 8 * EBST) * 2 + k2);
            #pragma unroll
            for (int n8 = 0; n8 < 10; n8++) MMA16816(acc[n8], ah, blf[n8]);
        }
    }

    float* Rt = g_Racc[t];
    int g4 = lane >> 2, t4 = lane & 3;
    int r0 = mw * 16 + g4;
    #pragma unroll
    for (int n8 = 0; n8 < 10; n8++) {
        int eo = nh * 160 + nw * 80 + n8 * 8 + t4 * 2;
        if (eo < 300) {
            Rt[(size_t)(s * 48 + r0) * 300 + eo]     = acc[n8][0];
            Rt[(size_t)(s * 48 + r0 + 8) * 300 + eo] = acc[n8][2];
        }
        if (eo + 1 < 300) {
            Rt[(size_t)(s * 48 + r0) * 300 + eo + 1]     = acc[n8][1];
            Rt[(size_t)(s * 48 + r0 + 8) * 300 + eo + 1] = acc[n8][3];
        }
    }
}

// finalize_enc: g_R = tanh(sum_t g_Racc[t] + conv_b). grid 6144, block 320.
__global__ __launch_bounds__(320) void finalize_enc(const float* __restrict__ conv_b) {
    int sr = blockIdx.x, f = threadIdx.x;
    if (f < 300) {
        size_t o = (size_t)sr * 300 + f;
        float v = g_Racc[0][o] + g_Racc[1][o] + g_Racc[2][o];
        g_R[o] = tanhf(v + conv_b[f]);
    }
}

// ---------------------------------------------------------------------------
// joint_tc_t<NI>: HMMA fp16 3-term fused joint GEMM + atomic masked max.
// NI = n8 tiles per warp (7 -> N=112 for fc 0,1 ; 5 -> N=80 for fc=2).
// K = 608 (9.5 chunks of 64; k 600..607 zero-padded).
// 256 threads (8 warps 4Mx2N). M = 128 pairs (8 i x 16 j).
// ---------------------------------------------------------------------------
#define AST 72
#define BST 72
#define JST 116
#define OF_BH 0
#define OF_BL 16384
#define OF_AH 32768
#define OF_AL 51200
#define OF_R1 69632
#define OF_R2 79360
#define SMB_TOTAL 98816

template<int NI>
__global__ __launch_bounds__(256) void joint_tc_t(
    const int* __restrict__ q1_len, const int* __restrict__ q2_len)
{
    int it, fc;
    if (NI == 7) { it = blockIdx.x >> 1; fc = blockIdx.x & 1; }
    else         { it = blockIdx.x;      fc = 2; }
    int jt = blockIdx.y, b = blockIdx.z;
    int l1 = q1_len[b], l2 = q2_len[b];
    if (it * 8 >= l1 || jt * 16 >= l2) return;

    extern __shared__ char smc[];
    __half* sBh = (__half*)(smc + OF_BH);
    __half* sBl = (__half*)(smc + OF_BL);
    __half* sAh = (__half*)(smc + OF_AH);
    __half* sAl = (__half*)(smc + OF_AL);
    float* r1s = (float*)(smc + OF_R1);   // [8][304]
    float* r2s = (float*)(smc + OF_R2);   // [16][304]
    float* smJ = (float*)smc;             // epilogue reuse

    int tid = threadIdx.x;
    int warp = tid >> 5, lane = tid & 31;
    int nw = warp & 1, mw = warp >> 1;
    const int NROWS = NI * 16;            // staged B rows (112 or 80)

    {
        const float4* R1 = (const float4*)(g_R + (size_t)(b * 48 + it * 8) * 300);
        const float4* R2 = (const float4*)(g_R + (size_t)((64 + b) * 48 + jt * 16) * 300);
        for (int i = tid; i < 8 * 75; i += 256) {
            int r = i / 75, c = i - r * 75;
            ((float4*)(r1s + r * 304))[c] = R1[r * 75 + c];
        }
        for (int i = tid; i < 16 * 75; i += 256) {
            int r = i / 75, c = i - r * 75;
            ((float4*)(r2s + r * 304))[c] = R2[r * 75 + c];
        }
    }

    float acc[2][NI][4];
    #pragma unroll
    for (int mi = 0; mi < 2; mi++)
        #pragma unroll
        for (int ni = 0; ni < NI; ni++)
            #pragma unroll
            for (int v = 0; v < 4; v++) acc[mi][ni][v] = 0.f;

    uint32_t sbase = smem_u32(smc);
    int arow = mw * 32 + (lane & 15);
    int acol = (lane >> 4) << 3;
    uint32_t aAh0 = sbase + OF_AH + (uint32_t)(arow * AST + acol) * 2;
    uint32_t aAh1 = aAh0 + 16 * AST * 2;
    uint32_t aAl0 = sbase + OF_AL + (uint32_t)(arow * AST + acol) * 2;
    uint32_t aAl1 = aAl0 + 16 * AST * 2;
    int brow = nw * (NI * 8) + (lane & 7);
    int bcol = lane & 8;
    uint32_t aBh = sbase + OF_BH + (uint32_t)(brow * BST + bcol) * 2;
    uint32_t aBl = sbase + OF_BL + (uint32_t)(brow * BST + bcol) * 2;

    int fp_ = tid >> 1, fhalf = tid & 1;
    const float* r1p = r1s + (fp_ >> 4) * 304;
    const float* r2p = r2s + (fp_ & 15) * 304;
    __half2* fdh = (__half2*)(sAh + fp_ * AST + fhalf * 32);
    __half2* fdl = (__half2*)(sAl + fp_ * AST + fhalf * 32);

#define JOINT_KSTEP(K2) do { \
        uint32_t ah[2][4], al[2][4], bh[NI][2], bl[NI][2]; \
        LDSM4(ah[0], aAh0 + (K2)); \
        LDSM4(ah[1], aAh1 + (K2)); \
        _Pragma("unroll") \
        for (int n8 = 0; n8 < NI; n8++) LDSM2(bh[n8], aBh + (uint32_t)(n8 * 8 * BST) * 2 + (K2)); \
        _Pragma("unroll") \
        for (int mi = 0; mi < 2; mi++) \
            _Pragma("unroll") \
            for (int ni = 0; ni < NI; ni++) MMA16816(acc[mi][ni], ah[mi], bh[ni]); \
        LDSM4(al[0], aAl0 + (K2)); \
        LDSM4(al[1], aAl1 + (K2)); \
        _Pragma("unroll") \
        for (int mi = 0; mi < 2; mi++) \
            _Pragma("unroll") \
            for (int ni = 0; ni < NI; ni++) MMA16816(acc[mi][ni], al[mi], bh[ni]); \
        _Pragma("unroll") \
        for (int n8 = 0; n8 < NI; n8++) LDSM2(bl[n8], aBl + (uint32_t)(n8 * 8 * BST) * 2 + (K2)); \
        _Pragma("unroll") \
        for (int mi = 0; mi < 2; mi++) \
            _Pragma("unroll") \
            for (int ni = 0; ni < NI; ni++) MMA16816(acc[mi][ni], ah[mi], bl[ni]); \
    } while (0)

    for (int c = 0; c < 10; c++) {
        __syncthreads();
        {
            const uint4* srch = g_W4h + (size_t)(fc * 10 + c) * 896;
            const uint4* srcl = g_W4l + (size_t)(fc * 10 + c) * 896;
            for (int i = tid; i < NROWS * 8; i += 256) {
                int n = i >> 3, kk = i & 7;
                *(uint4*)(sBh + n * BST + kk * 8) = srch[i];
                *(uint4*)(sBl + n * BST + kk * 8) = srcl[i];
            }
        }
        if (c < 9 || fhalf == 0) {
            int kb = c * 64 + fhalf * 32;
            #pragma unroll
            for (int m = 0; m < 16; m++) {
                int e = kb + 2 * m;
                float v0, v1;
                if (e < 300)      { v0 = fabsf(r1p[e] - r2p[e]);      v1 = fabsf(r1p[e + 1] - r2p[e + 1]); }
                else if (e < 600) { v0 = r1p[e - 300] * r2p[e - 300]; v1 = (e + 1 < 600) ? r1p[e - 299] * r2p[e - 299] : 0.f; }
                else              { v0 = 0.f; v1 = 0.f; }
                __half h0 = __float2half_rn(v0), h1 = __float2half_rn(v1);
                fdh[m] = __halves2half2(h0, h1);
                fdl[m] = __halves2half2(__float2half_rn(v0 - __half2float(h0)),
                                        __float2half_rn(v1 - __half2float(h1)));
            }
        }
        __syncthreads();

        if (c < 9) {
            #pragma unroll
            for (int ks = 0; ks < 4; ks++) JOINT_KSTEP((uint32_t)(ks * 16) * 2);
        } else {
            // last chunk: only k 576..607 (2 k-steps)
            JOINT_KSTEP(0u);
            JOINT_KSTEP((uint32_t)(16 * 2));
        }
    }
#undef JOINT_KSTEP
    __syncthreads();

    {
        int r0 = mw * 32 + (lane >> 2);
        int c0 = nw * (NI * 8) + (lane & 3) * 2;
        #pragma unroll
        for (int mi = 0; mi < 2; mi++)
            #pragma unroll
            for (int ni = 0; ni < NI; ni++) {
                int r = r0 + mi * 16, cc = c0 + ni * 8;
                smJ[r * JST + cc]           = acc[mi][ni][0];
                smJ[r * JST + cc + 1]       = acc[mi][ni][1];
                smJ[(r + 8) * JST + cc]     = acc[mi][ni][2];
                smJ[(r + 8) * JST + cc + 1] = acc[mi][ni][3];
            }
    }
    __syncthreads();

    int fbase = fc * 112;
    int flim = (NI == 7) ? 112 : 76;     // fc=2 covers f 224..299
    int icnt = min(8, l1 - it * 8);
    int jcnt = min(16, l2 - jt * 16);

    for (int idx = tid; idx < icnt * flim; idx += 256) {
        int i = idx / flim, f = idx - i * flim;
        float v = smJ[(i * 16) * JST + f];
        for (int j = 1; j < jcnt; j++) v = fmaxf(v, smJ[(i * 16 + j) * JST + f]);
        int ig = it * 8 + i, fg = fbase + f;
        atomicMax(&g_Su[(size_t)(b * 48 + ig) * 304 + fg], enc_f(v));
    }
    for (int idx = tid; idx < jcnt * flim; idx += 256) {
        int j = idx / flim, f = idx - j * flim;
        float v = smJ[j * JST + f];
        for (int i = 1; i < icnt; i++) v = fmaxf(v, smJ[(i * 16 + j) * JST + f]);
        int jg = jt * 16 + j, fg = fbase + f;
        atomicMax(&g_Su[S2_OFF + (size_t)(b * 48 + jg) * 304 + fg], enc_f(v));
    }
}

// ---------------------------------------------------------------------------
// pool: decode s + tanh+bias ; attention softmax ; h -> g_H
// ---------------------------------------------------------------------------
__global__ __launch_bounds__(256) void pool_kernel(
    const int* __restrict__ q1_len, const int* __restrict__ q2_len,
    const float* __restrict__ att_w, const float* __restrict__ att_b,
    const float* __restrict__ fc0_b)
{
    int side = blockIdx.x, b = blockIdx.y;
    int l1 = q1_len[b], l2 = q2_len[b];
    int len = side ? l2 : l1;
    const unsigned* Sb = g_Su + (size_t)side * S2_OFF + (size_t)b * 48 * 304;

    extern __shared__ float sm[];
    float* sv = sm;              // [48][301]
    float* lg = sv + 48 * 301;   // [48]
    int tid = threadIdx.x;

    for (int idx = tid; idx < len * 300; idx += 256) {
        int l = idx / 300, f = idx - l * 300;
        sv[l * 301 + f] = tanhf(dec_f(Sb[(size_t)l * 304 + f]) + fc0_b[f]);
    }
    __syncthreads();

    int lane = tid & 31, warp = tid >> 5;
    const float* Rbase = g_R + (size_t)(side * 64 + b) * 48 * 300;
    for (int l = warp; l < len; l += 8) {
        float a = 0.f;
        for (int e = lane; e < 300; e += 32) {
            a += att_w[e]       * Rbase[l * 300 + e];
            a += att_w[300 + e] * sv[l * 301 + e];
        }
        #pragma unroll
        for (int d = 16; d; d >>= 1) a += __shfl_xor_sync(0xffffffffu, a, d);
        if (lane == 0) lg[l] = a + att_b[0];
    }
    __syncthreads();

    if (warp == 0) {
        float v0 = (lane < len) ? lg[lane] : NEGV;
        float v1 = (lane + 32 < len) ? lg[lane + 32] : NEGV;
        float mx = fmaxf(v0, v1);
        #pragma unroll
        for (int d = 16; d; d >>= 1) mx = fmaxf(mx, __shfl_xor_sync(0xffffffffu, mx, d));
        float e0 = (lane < len) ? expf(v0 - mx) : 0.f;
        float e1 = (lane + 32 < len) ? expf(v1 - mx) : 0.f;
        float s = e0 + e1;
        #pragma unroll
        for (int d = 16; d; d >>= 1) s += __shfl_xor_sync(0xffffffffu, s, d);
        float inv = 1.f / s;
        if (lane < len) lg[lane] = e0 * inv;
        if (lane + 32 < len) lg[lane + 32] = e1 * inv;
    }
    __syncthreads();

    for (int f = tid; f < 300; f += 256) {
        float h = 0.f;
        for (int l = 0; l < len; l++) h += lg[l] * sv[l * 301 + f];
        g_H[b * 600 + side * 300 + f] = h;
    }
}

// ---------------------------------------------------------------------------
// head1: jv = tanh(H @ fc1_w^T + b). grid (64, 5), block 256.
// ---------------------------------------------------------------------------
__global__ __launch_bounds__(256) void head1_kernel(
    const float* __restrict__ fc1_w, const float* __restrict__ fc1_b)
{
    __shared__ float Hs[600];
    __shared__ float part[256];
    int b = blockIdx.x, fb = blockIdx.y;
    int tid = threadIdx.x;
    for (int i = tid; i < 600; i += 256) Hs[i] = g_H[b * 600 + i];
    __syncthreads();
    int fl = tid >> 2, seg = tid & 3;
    int f = fb * 60 + fl;
    float acc = 0.f;
    if (fl < 60) {
        const float* w = fc1_w + (size_t)f * 600 + seg * 150;
        const float* h = Hs + seg * 150;
        #pragma unroll 6
        for (int k = 0; k < 150; k++) acc += h[k] * w[k];
    }
    part[tid] = acc;
    __syncthreads();
    if (seg == 0 && fl < 60) {
        float s = part[tid] + part[tid + 1] + part[tid + 2] + part[tid + 3];
        g_J[b * 300 + f] = tanhf(s + fc1_b[f]);
    }
}

// head2: out = jv @ fc2_w^T + b. grid 64, block 64.
__global__ __launch_bounds__(64) void head2_kernel(
    const float* __restrict__ fc2_w, const float* __restrict__ fc2_b,
    float* __restrict__ out)
{
    int b = blockIdx.x, tid = threadIdx.x;
    int c = tid >> 5, lane = tid & 31;
    float acc = 0.f;
    for (int f = lane; f < 300; f += 32)
        acc += g_J[b * 300 + f] * fc2_w[c * 300 + f];
    #pragma unroll
    for (int d = 16; d; d >>= 1) acc += __shfl_xor_sync(0xffffffffu, acc, d);
    if (lane == 0) out[b * 2 + c] = acc + fc2_b[c];
}

// ---------------------------------------------------------------------------
extern "C" void kernel_launch(void* const* d_in, const int* in_sizes, int n_in,
                              void* d_out, int out_size)
{
    const int*   q1     = (const int*)d_in[0];
    const int*   q2     = (const int*)d_in[1];
    const int*   q1_len = (const int*)d_in[2];
    const int*   q2_len = (const int*)d_in[3];
    const float* emb    = (const float*)d_in[4];
    const float* conv_w = (const float*)d_in[5];
    const float* conv_b = (const float*)d_in[6];
    const float* fc0_w  = (const float*)d_in[7];
    const float* fc0_b  = (const float*)d_in[8];
    const float* fc1_w  = (const float*)d_in[9];
    const float* fc1_b  = (const float*)d_in[10];
    const float* fc2_w  = (const float*)d_in[11];
    const float* fc2_b  = (const float*)d_in[12];
    const float* att_w  = (const float*)d_in[13];
    const float* att_b  = (const float*)d_in[14];
    float* out = (float*)d_out;

    const int smC = 48 * 301 * 4 + 48 * 4;

    cudaFuncSetAttribute(encode_tc,     cudaFuncAttributeMaxDynamicSharedMemorySize, SME_TOTAL);
    cudaFuncSetAttribute(joint_tc_t<7>, cudaFuncAttributeMaxDynamicSharedMemorySize, SMB_TOTAL);
    cudaFuncSetAttribute(joint_tc_t<5>, cudaFuncAttributeMaxDynamicSharedMemorySize, SMB_TOTAL);
    cudaFuncSetAttribute(pool_kernel,   cudaFuncAttributeMaxDynamicSharedMemorySize, smC);

    prep_w<<<dim3(30, 112), 64>>>(fc0_w);
    prep_cw<<<dim3(3, 320), 320>>>(conv_w);
    init_s<<<7296, 256>>>();
    encode_tc<<<dim3(128, 2, 3), 192, SME_TOTAL>>>(q1, q2, emb);
    finalize_enc<<<6144, 320>>>(conv_b);
    joint_tc_t<7><<<dim3(12, 3, 64), 256, SMB_TOTAL>>>(q1_len, q2_len);
    joint_tc_t<5><<<dim3(6, 3, 64), 256, SMB_TOTAL>>>(q1_len, q2_len);
    pool_kernel<<<dim3(2, 64), 256, smC>>>(q1_len, q2_len, att_w, att_b, fc0_b);
    head1_kernel<<<dim3(64, 5), 256>>>(fc1_w, fc1_b);
    head2_kernel<<<64, 64>>>(fc2_w, fc2_b, out);
    (void)in_sizes; (void)n_in; (void)out_size;
}

// round 8
// speedup vs baseline: 1.0883x; 1.0883x over previous
#include <cuda_runtime.h>
#include <cuda_fp16.h>
#include <cstdint>
#include <math.h>

#define BATCH 64
#define LSEQ  48
#define EDIM  300
#define F0DIM 300
#define NEGV  (-1000000000.0f)

// ---------------- helpers ----------------
__device__ __forceinline__ uint32_t smem_u32(const void* p) {
    uint32_t a;
    asm("{ .reg .u64 t; cvta.to.shared.u64 t, %1; cvt.u32.u64 %0, t; }"
        : "=r"(a) : "l"(p));
    return a;
}
#define LDSM4(r, addr) \
    asm volatile("ldmatrix.sync.aligned.m8n8.x4.shared.b16 {%0,%1,%2,%3}, [%4];" \
        : "=r"((r)[0]), "=r"((r)[1]), "=r"((r)[2]), "=r"((r)[3]) : "r"(addr))
#define LDSM2(r, addr) \
    asm volatile("ldmatrix.sync.aligned.m8n8.x2.shared.b16 {%0,%1}, [%2];" \
        : "=r"((r)[0]), "=r"((r)[1]) : "r"(addr))
#define MMA16816(c, a, bb) \
    asm volatile("mma.sync.aligned.m16n8k16.row.col.f32.f16.f16.f32 " \
        "{%0,%1,%2,%3}, {%4,%5,%6,%7}, {%8,%9}, {%0,%1,%2,%3};" \
        : "+f"((c)[0]), "+f"((c)[1]), "+f"((c)[2]), "+f"((c)[3]) \
        : "r"((a)[0]), "r"((a)[1]), "r"((a)[2]), "r"((a)[3]), \
          "r"((bb)[0]), "r"((bb)[1]))

// order-preserving float<->uint for atomic max
__device__ __forceinline__ unsigned enc_f(float x) {
    unsigned u = __float_as_uint(x);
    return (u & 0x80000000u) ? ~u : (u | 0x80000000u);
}
__device__ __forceinline__ float dec_f(unsigned k) {
    unsigned u = (k & 0x80000000u) ? (k & 0x7fffffffu) : ~k;
    return __uint_as_float(u);
}

// ---------------- global scratch ----------------
__device__ float g_R[128 * LSEQ * EDIM];            // r1 (0..63), r2 (64..127)
__device__ unsigned g_Su[2 * 64 * 48 * 304];        // s1 | s2 encoded max (pre-tanh)
__device__ float g_H[64 * 600];
__device__ float g_J[64 * 300];
// pre-gathered embeddings fp16 hi/lo: [s(128)][50 rows][320], pads zeroed
__device__ __half g_Xh[128 * 50 * 320];
__device__ __half g_Xl[128 * 50 * 320];
// fc0 weights, fp16 hi/lo split, layout [fc(3)][chunk(10)][n(112)][k(64)]
__device__ uint4 g_W4h[3 * 10 * 112 * 64 / 8];
__device__ uint4 g_W4l[3 * 10 * 112 * 64 / 8];
// conv weights, fp16 hi/lo, layout [t(3)][n(320)][k(320)]
__device__ __half g_CWh[3 * 320 * 320];
__device__ __half g_CWl[3 * 320 * 320];

#define S2_OFF (64 * 48 * 304)   // 933888

// ---------------------------------------------------------------------------
// prep_w: fc0_w -> fp16 hi/lo split in joint CTA-chunk layout
// ---------------------------------------------------------------------------
__global__ void prep_w(const float* __restrict__ fc0_w) {
    int fcc = blockIdx.x;           // fc*10 + c
    int fc = fcc / 10, c = fcc % 10;
    int n = blockIdx.y, k = threadIdx.x;
    int f = fc * 112 + n;
    int kg = c * 64 + k;
    float v = (f < 300 && kg < 600) ? fc0_w[(size_t)f * 600 + kg] : 0.f;
    __half h = __float2half_rn(v);
    __half l = __float2half_rn(v - __half2float(h));
    size_t idx = ((size_t)fcc * 112 + n) * 64 + k;
    ((__half*)g_W4h)[idx] = h;
    ((__half*)g_W4l)[idx] = l;
}

// prep_cw: conv_w (E,E,3) -> W_t[n=eo][k=ei] fp16 hi/lo, zero-padded to 320x320
__global__ void prep_cw(const float* __restrict__ conv_w) {
    int t = blockIdx.x, n = blockIdx.y, k = threadIdx.x;
    float v = (n < 300 && k < 300) ? conv_w[(size_t)n * 900 + k * 3 + t] : 0.f;
    __half h = __float2half_rn(v);
    __half l = __float2half_rn(v - __half2float(h));
    size_t idx = ((size_t)t * 320 + n) * 320 + k;
    g_CWh[idx] = h;
    g_CWl[idx] = l;
}

// init_s: seed encoded NEG
__global__ void init_s() {
    unsigned idx = blockIdx.x * 256 + threadIdx.x;
    if (idx < 2u * S2_OFF) g_Su[idx] = ~__float_as_uint(NEGV);
}

// gather_x: one-time embedding gather + fp16 hi/lo convert, pads zeroed.
// grid 128, block 256. Row r = x[r-1]; rows 0/49 and cols 300..319 are zero.
__global__ __launch_bounds__(256) void gather_x(
    const int* __restrict__ q1, const int* __restrict__ q2,
    const float* __restrict__ emb)
{
    int s = blockIdx.x;
    int b = s & 63;
    bool side = s >= 64;
    const int* q = side ? q2 : q1;
    __shared__ int toks[48];
    int tid = threadIdx.x;
    if (tid < 48) toks[tid] = q[b * 48 + tid];
    __syncthreads();
    size_t base = (size_t)s * 50 * 320;
    for (int idx = tid; idx < 50 * 320; idx += 256) {
        int row = idx / 320, col = idx - row * 320;
        float v = 0.f;
        if (row >= 1 && row <= 48 && col < 300)
            v = emb[(size_t)toks[row - 1] * 300 + col];
        __half h = __float2half_rn(v);
        g_Xh[base + idx] = h;
        g_Xl[base + idx] = __float2half_rn(v - __half2float(h));
    }
}

// ---------------------------------------------------------------------------
// encode_tc: HMMA conv1d. y = tanh(sum_t shift_t(X) @ W_t^T + b)
// grid (128, 2): x = s, y = nh (eo half of 160). 192 threads (3M x 2N warps).
// Prologue is a coalesced uint4 copy of pre-gathered g_X (L2-resident).
// ---------------------------------------------------------------------------
#define XSTR 328
#define EBST 72
#define OF_XH 0
#define OF_XL 32800
#define OF_EBH 65600
#define OF_EBL 88640
#define SME_TOTAL 111680

__global__ __launch_bounds__(192) void encode_tc(const float* __restrict__ conv_b)
{
    int s = blockIdx.x, nh = blockIdx.y;
    extern __shared__ char smc[];
    __half* sbh = (__half*)(smc + OF_EBH); // [160][EBST]
    __half* sbl = (__half*)(smc + OF_EBL);
    int tid = threadIdx.x, warp = tid >> 5, lane = tid & 31;

    // copy X hi+lo from global (50 rows x 40 uint4 each)
    {
        const uint4* srch = (const uint4*)(g_Xh + (size_t)s * 16000);
        const uint4* srcl = (const uint4*)(g_Xl + (size_t)s * 16000);
        for (int i = tid; i < 50 * 40; i += 192) {
            int row = i / 40, c = i - row * 40;
            *(uint4*)(smc + OF_XH + row * (XSTR * 2) + c * 16) = srch[i];
            *(uint4*)(smc + OF_XL + row * (XSTR * 2) + c * 16) = srcl[i];
        }
    }

    int mw = warp >> 1, nw = warp & 1;
    float acc[10][4];
    #pragma unroll
    for (int n8 = 0; n8 < 10; n8++)
        #pragma unroll
        for (int v = 0; v < 4; v++) acc[n8][v] = 0.f;

    uint32_t sbase = smem_u32(smc);
    uint32_t aXh = sbase + OF_XH + (uint32_t)((mw * 16 + (lane & 15)) * XSTR + ((lane >> 4) << 3)) * 2;
    uint32_t aXl = aXh + (OF_XL - OF_XH);
    uint32_t aBh = sbase + OF_EBH + (uint32_t)((nw * 80 + (lane & 7)) * EBST + (lane & 8)) * 2;
    uint32_t aBl = aBh + (OF_EBL - OF_EBH);

    for (int t = 0; t < 3; t++) {
        const __half* gwh = g_CWh + ((size_t)t * 320 + nh * 160) * 320;
        const __half* gwl = g_CWl + ((size_t)t * 320 + nh * 160) * 320;
        for (int c = 0; c < 5; c++) {
            __syncthreads();
            {
                const uint4* sh = (const uint4*)(gwh + c * 64);
                const uint4* sl = (const uint4*)(gwl + c * 64);
                for (int i = tid; i < 160 * 8; i += 192) {
                    int n = i >> 3, kk = i & 7;
                    *(uint4*)(sbh + n * EBST + kk * 8) = sh[n * 40 + kk];
                    *(uint4*)(sbl + n * EBST + kk * 8) = sl[n * 40 + kk];
                }
            }
            __syncthreads();
            uint32_t aoff = (uint32_t)(t * XSTR + c * 64) * 2;
            #pragma unroll
            for (int ks = 0; ks < 4; ks++) {
                uint32_t k2 = ks * 32;
                uint32_t ah[4], al[4], bhf[10][2], blf[10][2];
                LDSM4(ah, aXh + aoff + k2);
                LDSM4(al, aXl + aoff + k2);
                #pragma unroll
                for (int n8 = 0; n8 < 10; n8++) LDSM2(bhf[n8], aBh + (uint32_t)(n8 * 8 * EBST) * 2 + k2);
                #pragma unroll
                for (int n8 = 0; n8 < 10; n8++) MMA16816(acc[n8], ah, bhf[n8]);
                #pragma unroll
                for (int n8 = 0; n8 < 10; n8++) MMA16816(acc[n8], al, bhf[n8]);
                #pragma unroll
                for (int n8 = 0; n8 < 10; n8++) LDSM2(blf[n8], aBl + (uint32_t)(n8 * 8 * EBST) * 2 + k2);
                #pragma unroll
                for (int n8 = 0; n8 < 10; n8++) MMA16816(acc[n8], ah, blf[n8]);
            }
        }
    }

    int g4 = lane >> 2, t4 = lane & 3;
    int r0 = mw * 16 + g4;
    #pragma unroll
    for (int n8 = 0; n8 < 10; n8++) {
        int eo = nh * 160 + nw * 80 + n8 * 8 + t4 * 2;
        if (eo < 300) {
            float bi = conv_b[eo];
            g_R[(size_t)(s * 48 + r0) * 300 + eo]     = tanhf(acc[n8][0] + bi);
            g_R[(size_t)(s * 48 + r0 + 8) * 300 + eo] = tanhf(acc[n8][2] + bi);
        }
        if (eo + 1 < 300) {
            float bi = conv_b[eo + 1];
            g_R[(size_t)(s * 48 + r0) * 300 + eo + 1]     = tanhf(acc[n8][1] + bi);
            g_R[(size_t)(s * 48 + r0 + 8) * 300 + eo + 1] = tanhf(acc[n8][3] + bi);
        }
    }
}

// ---------------------------------------------------------------------------
// joint_tc_t<NI>: HMMA fp16 3-term fused joint GEMM + atomic masked max.
// NI = n8 tiles per warp (7 -> N=112 for fc 0,1 ; 5 -> N=80 for fc=2).
// K = 608 (9.5 chunks of 64). 256 threads (8 warps 4Mx2N). M=128 pairs.
// ---------------------------------------------------------------------------
#define AST 72
#define BST 72
#define JST 116
#define OF_BH 0
#define OF_BL 16384
#define OF_AH 32768
#define OF_AL 51200
#define OF_R1 69632
#define OF_R2 79360
#define SMB_TOTAL 98816

template<int NI>
__global__ __launch_bounds__(256) void joint_tc_t(
    const int* __restrict__ q1_len, const int* __restrict__ q2_len)
{
    int it, fc;
    if (NI == 7) { it = blockIdx.x >> 1; fc = blockIdx.x & 1; }
    else         { it = blockIdx.x;      fc = 2; }
    int jt = blockIdx.y, b = blockIdx.z;
    int l1 = q1_len[b], l2 = q2_len[b];
    if (it * 8 >= l1 || jt * 16 >= l2) return;

    extern __shared__ char smc[];
    __half* sBh = (__half*)(smc + OF_BH);
    __half* sBl = (__half*)(smc + OF_BL);
    __half* sAh = (__half*)(smc + OF_AH);
    __half* sAl = (__half*)(smc + OF_AL);
    float* r1s = (float*)(smc + OF_R1);   // [8][304]
    float* r2s = (float*)(smc + OF_R2);   // [16][304]
    float* smJ = (float*)smc;             // epilogue reuse

    int tid = threadIdx.x;
    int warp = tid >> 5, lane = tid & 31;
    int nw = warp & 1, mw = warp >> 1;
    const int NROWS = NI * 16;            // staged B rows (112 or 80)

    {
        const float4* R1 = (const float4*)(g_R + (size_t)(b * 48 + it * 8) * 300);
        const float4* R2 = (const float4*)(g_R + (size_t)((64 + b) * 48 + jt * 16) * 300);
        for (int i = tid; i < 8 * 75; i += 256) {
            int r = i / 75, c = i - r * 75;
            ((float4*)(r1s + r * 304))[c] = R1[r * 75 + c];
        }
        for (int i = tid; i < 16 * 75; i += 256) {
            int r = i / 75, c = i - r * 75;
            ((float4*)(r2s + r * 304))[c] = R2[r * 75 + c];
        }
    }

    float acc[2][NI][4];
    #pragma unroll
    for (int mi = 0; mi < 2; mi++)
        #pragma unroll
        for (int ni = 0; ni < NI; ni++)
            #pragma unroll
            for (int v = 0; v < 4; v++) acc[mi][ni][v] = 0.f;

    uint32_t sbase = smem_u32(smc);
    int arow = mw * 32 + (lane & 15);
    int acol = (lane >> 4) << 3;
    uint32_t aAh0 = sbase + OF_AH + (uint32_t)(arow * AST + acol) * 2;
    uint32_t aAh1 = aAh0 + 16 * AST * 2;
    uint32_t aAl0 = sbase + OF_AL + (uint32_t)(arow * AST + acol) * 2;
    uint32_t aAl1 = aAl0 + 16 * AST * 2;
    int brow = nw * (NI * 8) + (lane & 7);
    int bcol = lane & 8;
    uint32_t aBh = sbase + OF_BH + (uint32_t)(brow * BST + bcol) * 2;
    uint32_t aBl = sbase + OF_BL + (uint32_t)(brow * BST + bcol) * 2;

    int fp_ = tid >> 1, fhalf = tid & 1;
    const float* r1p = r1s + (fp_ >> 4) * 304;
    const float* r2p = r2s + (fp_ & 15) * 304;
    __half2* fdh = (__half2*)(sAh + fp_ * AST + fhalf * 32);
    __half2* fdl = (__half2*)(sAl + fp_ * AST + fhalf * 32);

#define JOINT_KSTEP(K2) do { \
        uint32_t ah[2][4], al[2][4], bh[NI][2], bl[NI][2]; \
        LDSM4(ah[0], aAh0 + (K2)); \
        LDSM4(ah[1], aAh1 + (K2)); \
        _Pragma("unroll") \
        for (int n8 = 0; n8 < NI; n8++) LDSM2(bh[n8], aBh + (uint32_t)(n8 * 8 * BST) * 2 + (K2)); \
        _Pragma("unroll") \
        for (int mi = 0; mi < 2; mi++) \
            _Pragma("unroll") \
            for (int ni = 0; ni < NI; ni++) MMA16816(acc[mi][ni], ah[mi], bh[ni]); \
        LDSM4(al[0], aAl0 + (K2)); \
        LDSM4(al[1], aAl1 + (K2)); \
        _Pragma("unroll") \
        for (int mi = 0; mi < 2; mi++) \
            _Pragma("unroll") \
            for (int ni = 0; ni < NI; ni++) MMA16816(acc[mi][ni], al[mi], bh[ni]); \
        _Pragma("unroll") \
        for (int n8 = 0; n8 < NI; n8++) LDSM2(bl[n8], aBl + (uint32_t)(n8 * 8 * BST) * 2 + (K2)); \
        _Pragma("unroll") \
        for (int mi = 0; mi < 2; mi++) \
            _Pragma("unroll") \
            for (int ni = 0; ni < NI; ni++) MMA16816(acc[mi][ni], ah[mi], bl[ni]); \
    } while (0)

    for (int c = 0; c < 10; c++) {
        __syncthreads();
        {
            const uint4* srch = g_W4h + (size_t)(fc * 10 + c) * 896;
            const uint4* srcl = g_W4l + (size_t)(fc * 10 + c) * 896;
            for (int i = tid; i < NROWS * 8; i += 256) {
                int n = i >> 3, kk = i & 7;
                *(uint4*)(sBh + n * BST + kk * 8) = srch[i];
                *(uint4*)(sBl + n * BST + kk * 8) = srcl[i];
            }
        }
        if (c < 9 || fhalf == 0) {
            int kb = c * 64 + fhalf * 32;
            #pragma unroll
            for (int m = 0; m < 16; m++) {
                int e = kb + 2 * m;
                float v0, v1;
                if (e < 300)      { v0 = fabsf(r1p[e] - r2p[e]);      v1 = fabsf(r1p[e + 1] - r2p[e + 1]); }
                else if (e < 600) { v0 = r1p[e - 300] * r2p[e - 300]; v1 = (e + 1 < 600) ? r1p[e - 299] * r2p[e - 299] : 0.f; }
                else              { v0 = 0.f; v1 = 0.f; }
                __half h0 = __float2half_rn(v0), h1 = __float2half_rn(v1);
                fdh[m] = __halves2half2(h0, h1);
                fdl[m] = __halves2half2(__float2half_rn(v0 - __half2float(h0)),
                                        __float2half_rn(v1 - __half2float(h1)));
            }
        }
        __syncthreads();

        if (c < 9) {
            #pragma unroll
            for (int ks = 0; ks < 4; ks++) JOINT_KSTEP((uint32_t)(ks * 16) * 2);
        } else {
            JOINT_KSTEP(0u);
            JOINT_KSTEP((uint32_t)(16 * 2));
        }
    }
#undef JOINT_KSTEP
    __syncthreads();

    {
        int r0 = mw * 32 + (lane >> 2);
        int c0 = nw * (NI * 8) + (lane & 3) * 2;
        #pragma unroll
        for (int mi = 0; mi < 2; mi++)
            #pragma unroll
            for (int ni = 0; ni < NI; ni++) {
                int r = r0 + mi * 16, cc = c0 + ni * 8;
                smJ[r * JST + cc]           = acc[mi][ni][0];
                smJ[r * JST + cc + 1]       = acc[mi][ni][1];
                smJ[(r + 8) * JST + cc]     = acc[mi][ni][2];
                smJ[(r + 8) * JST + cc + 1] = acc[mi][ni][3];
            }
    }
    __syncthreads();

    int fbase = fc * 112;
    int flim = (NI == 7) ? 112 : 76;     // fc=2 covers f 224..299
    int icnt = min(8, l1 - it * 8);
    int jcnt = min(16, l2 - jt * 16);

    for (int idx = tid; idx < icnt * flim; idx += 256) {
        int i = idx / flim, f = idx - i * flim;
        float v = smJ[(i * 16) * JST + f];
        for (int j = 1; j < jcnt; j++) v = fmaxf(v, smJ[(i * 16 + j) * JST + f]);
        int ig = it * 8 + i, fg = fbase + f;
        atomicMax(&g_Su[(size_t)(b * 48 + ig) * 304 + fg], enc_f(v));
    }
    for (int idx = tid; idx < jcnt * flim; idx += 256) {
        int j = idx / flim, f = idx - j * flim;
        float v = smJ[j * JST + f];
        for (int i = 1; i < icnt; i++) v = fmaxf(v, smJ[(i * 16 + j) * JST + f]);
        int jg = jt * 16 + j, fg = fbase + f;
        atomicMax(&g_Su[S2_OFF + (size_t)(b * 48 + jg) * 304 + fg], enc_f(v));
    }
}

// ---------------------------------------------------------------------------
// pool: decode s + tanh+bias ; attention softmax ; h -> g_H
// ---------------------------------------------------------------------------
__global__ __launch_bounds__(256) void pool_kernel(
    const int* __restrict__ q1_len, const int* __restrict__ q2_len,
    const float* __restrict__ att_w, const float* __restrict__ att_b,
    const float* __restrict__ fc0_b)
{
    int side = blockIdx.x, b = blockIdx.y;
    int l1 = q1_len[b], l2 = q2_len[b];
    int len = side ? l2 : l1;
    const unsigned* Sb = g_Su + (size_t)side * S2_OFF + (size_t)b * 48 * 304;

    extern __shared__ float sm[];
    float* sv = sm;              // [48][301]
    float* lg = sv + 48 * 301;   // [48]
    int tid = threadIdx.x;

    for (int idx = tid; idx < len * 300; idx += 256) {
        int l = idx / 300, f = idx - l * 300;
        sv[l * 301 + f] = tanhf(dec_f(Sb[(size_t)l * 304 + f]) + fc0_b[f]);
    }
    __syncthreads();

    int lane = tid & 31, warp = tid >> 5;
    const float* Rbase = g_R + (size_t)(side * 64 + b) * 48 * 300;
    for (int l = warp; l < len; l += 8) {
        float a = 0.f;
        for (int e = lane; e < 300; e += 32) {
            a += att_w[e]       * Rbase[l * 300 + e];
            a += att_w[300 + e] * sv[l * 301 + e];
        }
        #pragma unroll
        for (int d = 16; d; d >>= 1) a += __shfl_xor_sync(0xffffffffu, a, d);
        if (lane == 0) lg[l] = a + att_b[0];
    }
    __syncthreads();

    if (warp == 0) {
        float v0 = (lane < len) ? lg[lane] : NEGV;
        float v1 = (lane + 32 < len) ? lg[lane + 32] : NEGV;
        float mx = fmaxf(v0, v1);
        #pragma unroll
        for (int d = 16; d; d >>= 1) mx = fmaxf(mx, __shfl_xor_sync(0xffffffffu, mx, d));
        float e0 = (lane < len) ? expf(v0 - mx) : 0.f;
        float e1 = (lane + 32 < len) ? expf(v1 - mx) : 0.f;
        float s = e0 + e1;
        #pragma unroll
        for (int d = 16; d; d >>= 1) s += __shfl_xor_sync(0xffffffffu, s, d);
        float inv = 1.f / s;
        if (lane < len) lg[lane] = e0 * inv;
        if (lane + 32 < len) lg[lane + 32] = e1 * inv;
    }
    __syncthreads();

    for (int f = tid; f < 300; f += 256) {
        float h = 0.f;
        for (int l = 0; l < len; l++) h += lg[l] * sv[l * 301 + f];
        g_H[b * 600 + side * 300 + f] = h;
    }
}

// ---------------------------------------------------------------------------
// head1: jv = tanh(H @ fc1_w^T + b). grid (64, 5), block 256.
// ---------------------------------------------------------------------------
__global__ __launch_bounds__(256) void head1_kernel(
    const float* __restrict__ fc1_w, const float* __restrict__ fc1_b)
{
    __shared__ float Hs[600];
    __shared__ float part[256];
    int b = blockIdx.x, fb = blockIdx.y;
    int tid = threadIdx.x;
    for (int i = tid; i < 600; i += 256) Hs[i] = g_H[b * 600 + i];
    __syncthreads();
    int fl = tid >> 2, seg = tid & 3;
    int f = fb * 60 + fl;
    float acc = 0.f;
    if (fl < 60) {
        const float* w = fc1_w + (size_t)f * 600 + seg * 150;
        const float* h = Hs + seg * 150;
        #pragma unroll 6
        for (int k = 0; k < 150; k++) acc += h[k] * w[k];
    }
    part[tid] = acc;
    __syncthreads();
    if (seg == 0 && fl < 60) {
        float s = part[tid] + part[tid + 1] + part[tid + 2] + part[tid + 3];
        g_J[b * 300 + f] = tanhf(s + fc1_b[f]);
    }
}

// head2: out = jv @ fc2_w^T + b. grid 64, block 64.
__global__ __launch_bounds__(64) void head2_kernel(
    const float* __restrict__ fc2_w, const float* __restrict__ fc2_b,
    float* __restrict__ out)
{
    int b = blockIdx.x, tid = threadIdx.x;
    int c = tid >> 5, lane = tid & 31;
    float acc = 0.f;
    for (int f = lane; f < 300; f += 32)
        acc += g_J[b * 300 + f] * fc2_w[c * 300 + f];
    #pragma unroll
    for (int d = 16; d; d >>= 1) acc += __shfl_xor_sync(0xffffffffu, acc, d);
    if (lane == 0) out[b * 2 + c] = acc + fc2_b[c];
}

// ---------------------------------------------------------------------------
extern "C" void kernel_launch(void* const* d_in, const int* in_sizes, int n_in,
                              void* d_out, int out_size)
{
    const int*   q1     = (const int*)d_in[0];
    const int*   q2     = (const int*)d_in[1];
    const int*   q1_len = (const int*)d_in[2];
    const int*   q2_len = (const int*)d_in[3];
    const float* emb    = (const float*)d_in[4];
    const float* conv_w = (const float*)d_in[5];
    const float* conv_b = (const float*)d_in[6];
    const float* fc0_w  = (const float*)d_in[7];
    const float* fc0_b  = (const float*)d_in[8];
    const float* fc1_w  = (const float*)d_in[9];
    const float* fc1_b  = (const float*)d_in[10];
    const float* fc2_w  = (const float*)d_in[11];
    const float* fc2_b  = (const float*)d_in[12];
    const float* att_w  = (const float*)d_in[13];
    const float* att_b  = (const float*)d_in[14];
    float* out = (float*)d_out;

    const int smC = 48 * 301 * 4 + 48 * 4;

    cudaFuncSetAttribute(encode_tc,     cudaFuncAttributeMaxDynamicSharedMemorySize, SME_TOTAL);
    cudaFuncSetAttribute(joint_tc_t<7>, cudaFuncAttributeMaxDynamicSharedMemorySize, SMB_TOTAL);
    cudaFuncSetAttribute(joint_tc_t<5>, cudaFuncAttributeMaxDynamicSharedMemorySize, SMB_TOTAL);
    cudaFuncSetAttribute(pool_kernel,   cudaFuncAttributeMaxDynamicSharedMemorySize, smC);

    prep_w<<<dim3(30, 112), 64>>>(fc0_w);
    prep_cw<<<dim3(3, 320), 320>>>(conv_w);
    init_s<<<7296, 256>>>();
    gather_x<<<128, 256>>>(q1, q2, emb);
    encode_tc<<<dim3(128, 2), 192, SME_TOTAL>>>(conv_b);
    joint_tc_t<7><<<dim3(12, 3, 64), 256, SMB_TOTAL>>>(q1_len, q2_len);
    joint_tc_t<5><<<dim3(6, 3, 64), 256, SMB_TOTAL>>>(q1_len, q2_len);
    pool_kernel<<<dim3(2, 64), 256, smC>>>(q1_len, q2_len, att_w, att_b, fc0_b);
    head1_kernel<<<dim3(64, 5), 256>>>(fc1_w, fc1_b);
    head2_kernel<<<64, 64>>>(fc2_w, fc2_b, out);
    (void)in_sizes; (void)n_in; (void)out_size;
}